// round 1
// baseline (speedup 1.0000x reference)
#include <cuda_runtime.h>

// ---------------------------------------------------------------------------
// GAT: 3 layers, N=50000 nodes, E=800000 edges, IN=128, H=4, D=32, C=40
// Pipeline per layer:
//   gemm z = x@Wc              (z buffer)
//   gemm out = x@Wl + bc       (out buffer; agg atomically accumulates on top)
//   eler: el/er = <z, al/ar> per (node, head); init mkey=-inf, s=0
//   edge_max: atomicMax over dst of leaky_relu(el[src]+er[dst])
//   edge_sum: atomicAdd exp(e - m[dst]) into s[dst]
//   edge_agg: warp/edge: alpha = exp(e-m)/s; out[dst] += alpha_h * z[src]
// BN+ReLU after layers 0,1; head-mean + bias after layer 2.
// ---------------------------------------------------------------------------

#define NMAX 50000
#define SLOPE 0.2f
#define BN_EPS 1e-5f

// ---------------- scratch (static __device__, no allocation) ----------------
__device__ __align__(16) float g_z  [NMAX * 160];
__device__ __align__(16) float g_buf[NMAX * 160];
__device__ __align__(16) float g_h  [NMAX * 128];
__device__ __align__(16) float g_el [NMAX * 4];
__device__ __align__(16) float g_er [NMAX * 4];
__device__ __align__(16) int   g_mkey[NMAX * 4];
__device__ __align__(16) float g_s  [NMAX * 4];
__device__ __align__(16) float g_bnsum[256];   // [0:128)=sum, [128:256)=sumsq

// ---------------- helpers ----------------
__device__ __forceinline__ unsigned long long pack2(float a, float b) {
    unsigned long long r;
    asm("mov.b64 %0, {%1, %2};" : "=l"(r) : "f"(a), "f"(b));
    return r;
}
__device__ __forceinline__ void fma2(unsigned long long& acc, unsigned long long a,
                                     unsigned long long b) {
    asm("fma.rn.f32x2 %0, %1, %2, %0;" : "+l"(acc) : "l"(a), "l"(b));
}
__device__ __forceinline__ float2 unpack2(unsigned long long v) {
    float2 f;
    asm("mov.b64 {%0, %1}, %2;" : "=f"(f.x), "=f"(f.y) : "l"(v));
    return f;
}
// order-preserving float->int key for atomicMax
__device__ __forceinline__ int f2key(float f) {
    int i = __float_as_int(f);
    return i >= 0 ? i : (i ^ 0x7FFFFFFF);
}
__device__ __forceinline__ float key2f(int k) {
    return __int_as_float(k >= 0 ? k : (k ^ 0x7FFFFFFF));
}
__device__ __forceinline__ float lrelu(float x) { return x >= 0.f ? x : SLOPE * x; }

// ---------------- GEMM: out[n, KOUT] = X[n,128] @ W[128,KOUT] (+bias) --------
// block: (KOUT/4, 8) threads, 32 rows per block, packed f32x2 FMA.
template <int KOUT>
__global__ void gemm_kernel(const float* __restrict__ X, const float* __restrict__ W,
                            const float* __restrict__ bias, float* __restrict__ out,
                            int n) {
    __shared__ __align__(16) float xs[32][33];
    __shared__ __align__(16) float ws[32][KOUT];
    const int tx  = threadIdx.x;               // 0..KOUT/4-1
    const int ty  = threadIdx.y;               // 0..7
    const int tid = ty * (KOUT / 4) + tx;
    const int nth = 8 * (KOUT / 4);
    const int row0 = blockIdx.x * 32;

    unsigned long long acc[4][2] = {};

    for (int k0 = 0; k0 < 128; k0 += 32) {
        for (int i = tid; i < 32 * 32; i += nth) {
            int r = i >> 5, c = i & 31;
            int gr = row0 + r;
            xs[r][c] = (gr < n) ? X[gr * 128 + k0 + c] : 0.f;
        }
        for (int i = tid; i < 32 * KOUT; i += nth) {
            int r = i / KOUT, c = i - r * KOUT;
            ws[r][c] = W[(k0 + r) * KOUT + c];
        }
        __syncthreads();
#pragma unroll 8
        for (int k = 0; k < 32; k++) {
            const float4 w4 = *(const float4*)&ws[k][tx * 4];
            const unsigned long long w01 = pack2(w4.x, w4.y);
            const unsigned long long w23 = pack2(w4.z, w4.w);
#pragma unroll
            for (int i = 0; i < 4; i++) {
                float xv = xs[ty * 4 + i][k];
                unsigned long long x2 = pack2(xv, xv);
                fma2(acc[i][0], x2, w01);
                fma2(acc[i][1], x2, w23);
            }
        }
        __syncthreads();
    }

#pragma unroll
    for (int i = 0; i < 4; i++) {
        int r = row0 + ty * 4 + i;
        if (r < n) {
            float2 a = unpack2(acc[i][0]);
            float2 b = unpack2(acc[i][1]);
            float4 o = make_float4(a.x, a.y, b.x, b.y);
            if (bias) {
                o.x += bias[tx * 4 + 0];
                o.y += bias[tx * 4 + 1];
                o.z += bias[tx * 4 + 2];
                o.w += bias[tx * 4 + 3];
            }
            *(float4*)&out[r * KOUT + tx * 4] = o;
        }
    }
}

// ---------------- el/er per (node, head); init softmax state ----------------
template <int FOUT>
__global__ void eler_kernel(const float* __restrict__ z, const float* __restrict__ al,
                            const float* __restrict__ ar, float* __restrict__ el,
                            float* __restrict__ er, int* __restrict__ mkey,
                            float* __restrict__ sbuf, int n) {
    int idx = blockIdx.x * blockDim.x + threadIdx.x;
    if (idx >= n * 4) return;
    int h = idx & 3;
    int node = idx >> 2;
    const float* zp = z + node * (4 * FOUT) + h * FOUT;
    const float* alp = al + h * FOUT;
    const float* arp = ar + h * FOUT;
    float sl = 0.f, sr = 0.f;
#pragma unroll
    for (int d = 0; d < FOUT; d++) {
        float v = zp[d];
        sl += v * alp[d];
        sr += v * arp[d];
    }
    el[idx] = sl;
    er[idx] = sr;
    mkey[idx] = (int)0x80000000;   // -inf key
    sbuf[idx] = 0.f;
}

// ---------------- edge softmax pass 1: segment max ---------------------------
__global__ void edge_max_kernel(const int* __restrict__ src, const int* __restrict__ dst,
                                const float* __restrict__ el, const float* __restrict__ er,
                                int* __restrict__ mkey, int E) {
    int e = blockIdx.x * blockDim.x + threadIdx.x;
    if (e >= E) return;
    int s = src[e], d = dst[e];
    float4 a = *(const float4*)&el[s * 4];
    float4 b = *(const float4*)&er[d * 4];
    atomicMax(&mkey[d * 4 + 0], f2key(lrelu(a.x + b.x)));
    atomicMax(&mkey[d * 4 + 1], f2key(lrelu(a.y + b.y)));
    atomicMax(&mkey[d * 4 + 2], f2key(lrelu(a.z + b.z)));
    atomicMax(&mkey[d * 4 + 3], f2key(lrelu(a.w + b.w)));
}

// ---------------- edge softmax pass 2: segment sum of exp --------------------
__global__ void edge_sum_kernel(const int* __restrict__ src, const int* __restrict__ dst,
                                const float* __restrict__ el, const float* __restrict__ er,
                                const int* __restrict__ mkey, float* __restrict__ sbuf,
                                int E) {
    int e = blockIdx.x * blockDim.x + threadIdx.x;
    if (e >= E) return;
    int s = src[e], d = dst[e];
    float4 a = *(const float4*)&el[s * 4];
    float4 b = *(const float4*)&er[d * 4];
    int4 mk = *(const int4*)&mkey[d * 4];
    atomicAdd(&sbuf[d * 4 + 0], __expf(lrelu(a.x + b.x) - key2f(mk.x)));
    atomicAdd(&sbuf[d * 4 + 1], __expf(lrelu(a.y + b.y) - key2f(mk.y)));
    atomicAdd(&sbuf[d * 4 + 2], __expf(lrelu(a.z + b.z) - key2f(mk.z)));
    atomicAdd(&sbuf[d * 4 + 3], __expf(lrelu(a.w + b.w) - key2f(mk.w)));
}

// ---------------- edge aggregation: out[dst] += alpha_h * z[src] -------------
template <int KOUT, int FOUT>
__global__ void edge_agg_kernel(const int* __restrict__ src, const int* __restrict__ dst,
                                const float* __restrict__ el, const float* __restrict__ er,
                                const int* __restrict__ mkey, const float* __restrict__ sbuf,
                                const float* __restrict__ z, float* __restrict__ out,
                                int E) {
    int warp = (blockIdx.x * blockDim.x + threadIdx.x) >> 5;
    int lane = threadIdx.x & 31;
    if (warp >= E) return;
    int s = src[warp], d = dst[warp];

    float alpha = 0.f;
    if (lane < 4) {
        float e = lrelu(el[s * 4 + lane] + er[d * 4 + lane]);
        float m = key2f(mkey[d * 4 + lane]);
        alpha = __expf(e - m) / sbuf[d * 4 + lane];
    }
    float a0 = __shfl_sync(0xFFFFFFFFu, alpha, 0);
    float a1 = __shfl_sync(0xFFFFFFFFu, alpha, 1);
    float a2 = __shfl_sync(0xFFFFFFFFu, alpha, 2);
    float a3 = __shfl_sync(0xFFFFFFFFu, alpha, 3);
    float ah[4] = {a0, a1, a2, a3};

    const float4* zp = (const float4*)&z[s * KOUT];
    float* op = &out[d * KOUT];
#pragma unroll
    for (int j4 = lane; j4 < KOUT / 4; j4 += 32) {
        float4 zv = zp[j4];
        float a = ah[(j4 * 4) / FOUT];
        int j = j4 * 4;
        atomicAdd(op + j + 0, zv.x * a);
        atomicAdd(op + j + 1, zv.y * a);
        atomicAdd(op + j + 2, zv.z * a);
        atomicAdd(op + j + 3, zv.w * a);
    }
}

// ---------------- BatchNorm + ReLU -------------------------------------------
__global__ void bn_init_kernel(float* __restrict__ sums) {
    sums[threadIdx.x] = 0.f;   // 256 threads
}

__global__ void bn_reduce_kernel(const float* __restrict__ x, float* __restrict__ sums,
                                 int n) {
    int c = threadIdx.x;                 // 128 columns
    int r0 = blockIdx.x * 256;
    int r1 = min(r0 + 256, n);
    float s = 0.f, s2 = 0.f;
    for (int r = r0; r < r1; r++) {
        float v = x[r * 128 + c];
        s += v;
        s2 += v * v;
    }
    atomicAdd(&sums[c], s);
    atomicAdd(&sums[128 + c], s2);
}

__global__ void bn_apply_kernel(const float* __restrict__ x, const float* __restrict__ sums,
                                const float* __restrict__ g, const float* __restrict__ b,
                                float* __restrict__ out, int n) {
    int idx = blockIdx.x * blockDim.x + threadIdx.x;
    if (idx >= n * 128) return;
    int c = idx & 127;
    float inv_n = 1.f / (float)n;
    float mean = sums[c] * inv_n;
    float var = sums[128 + c] * inv_n - mean * mean;
    float y = (x[idx] - mean) * rsqrtf(var + BN_EPS) * g[c] + b[c];
    out[idx] = y > 0.f ? y : 0.f;
}

// ---------------- final: mean over heads + bias ------------------------------
__global__ void final_kernel(const float* __restrict__ buf, const float* __restrict__ bias,
                             float* __restrict__ out, int n) {
    int idx = blockIdx.x * blockDim.x + threadIdx.x;
    if (idx >= n * 40) return;
    int node = idx / 40;
    int c = idx - node * 40;
    const float* p = buf + node * 160;
    float v = 0.25f * (p[c] + p[40 + c] + p[80 + c] + p[120 + c]) + bias[c];
    out[idx] = v;
}

// ---------------------------------------------------------------------------
extern "C" void kernel_launch(void* const* d_in, const int* in_sizes, int n_in,
                              void* d_out, int out_size) {
    const float* feat = (const float*)d_in[0];
    const int* src = (const int*)d_in[1];
    const int* dst = (const int*)d_in[2];
    const float* Wc0 = (const float*)d_in[3];
    const float* al0 = (const float*)d_in[4];
    const float* ar0 = (const float*)d_in[5];
    const float* bc0 = (const float*)d_in[6];
    const float* Wl0 = (const float*)d_in[7];
    const float* Wc1 = (const float*)d_in[8];
    const float* al1 = (const float*)d_in[9];
    const float* ar1 = (const float*)d_in[10];
    const float* bc1 = (const float*)d_in[11];
    const float* Wl1 = (const float*)d_in[12];
    const float* Wc2 = (const float*)d_in[13];
    const float* al2 = (const float*)d_in[14];
    const float* ar2 = (const float*)d_in[15];
    const float* bc2 = (const float*)d_in[16];
    const float* Wl2 = (const float*)d_in[17];
    const float* g0 = (const float*)d_in[18];
    const float* b0 = (const float*)d_in[19];
    const float* g1 = (const float*)d_in[20];
    const float* b1 = (const float*)d_in[21];
    const float* bias_last = (const float*)d_in[22];

    const int n = in_sizes[0] / 128;   // 50000
    const int E = in_sizes[1];         // 800000

    float *z, *buf, *hbuf, *el, *er, *sbuf, *bnsum;
    int* mkey;
    cudaGetSymbolAddress((void**)&z, g_z);
    cudaGetSymbolAddress((void**)&buf, g_buf);
    cudaGetSymbolAddress((void**)&hbuf, g_h);
    cudaGetSymbolAddress((void**)&el, g_el);
    cudaGetSymbolAddress((void**)&er, g_er);
    cudaGetSymbolAddress((void**)&mkey, g_mkey);
    cudaGetSymbolAddress((void**)&sbuf, g_s);
    cudaGetSymbolAddress((void**)&bnsum, g_bnsum);

    const int gemm_blocks = (n + 31) / 32;
    const int edge_blocks = (E + 255) / 256;
    const int agg_blocks = (E + 7) / 8;   // 8 warps (edges) per 256-thread block

    // ---------------- layer 0 (fout=32, KOUT=128) ----------------
    {
        dim3 b(32, 8);
        gemm_kernel<128><<<gemm_blocks, b>>>(feat, Wc0, nullptr, z, n);
        gemm_kernel<128><<<gemm_blocks, b>>>(feat, Wl0, bc0, buf, n);
        eler_kernel<32><<<(n * 4 + 255) / 256, 256>>>(z, al0, ar0, el, er, mkey, sbuf, n);
        edge_max_kernel<<<edge_blocks, 256>>>(src, dst, el, er, mkey, E);
        edge_sum_kernel<<<edge_blocks, 256>>>(src, dst, el, er, mkey, sbuf, E);
        edge_agg_kernel<128, 32><<<agg_blocks, 256>>>(src, dst, el, er, mkey, sbuf, z, buf, E);
        bn_init_kernel<<<1, 256>>>(bnsum);
        bn_reduce_kernel<<<(n + 255) / 256, 128>>>(buf, bnsum, n);
        bn_apply_kernel<<<(n * 128 + 255) / 256, 256>>>(buf, bnsum, g0, b0, hbuf, n);
    }
    // ---------------- layer 1 (fout=32, KOUT=128) ----------------
    {
        dim3 b(32, 8);
        gemm_kernel<128><<<gemm_blocks, b>>>(hbuf, Wc1, nullptr, z, n);
        gemm_kernel<128><<<gemm_blocks, b>>>(hbuf, Wl1, bc1, buf, n);
        eler_kernel<32><<<(n * 4 + 255) / 256, 256>>>(z, al1, ar1, el, er, mkey, sbuf, n);
        edge_max_kernel<<<edge_blocks, 256>>>(src, dst, el, er, mkey, E);
        edge_sum_kernel<<<edge_blocks, 256>>>(src, dst, el, er, mkey, sbuf, E);
        edge_agg_kernel<128, 32><<<agg_blocks, 256>>>(src, dst, el, er, mkey, sbuf, z, buf, E);
        bn_init_kernel<<<1, 256>>>(bnsum);
        bn_reduce_kernel<<<(n + 255) / 256, 128>>>(buf, bnsum, n);
        bn_apply_kernel<<<(n * 128 + 255) / 256, 256>>>(buf, bnsum, g1, b1, hbuf, n);
    }
    // ---------------- layer 2 (fout=40, KOUT=160) ----------------
    {
        dim3 b(40, 8);
        gemm_kernel<160><<<gemm_blocks, b>>>(hbuf, Wc2, nullptr, z, n);
        gemm_kernel<160><<<gemm_blocks, b>>>(hbuf, Wl2, bc2, buf, n);
        eler_kernel<40><<<(n * 4 + 255) / 256, 256>>>(z, al2, ar2, el, er, mkey, sbuf, n);
        edge_max_kernel<<<edge_blocks, 256>>>(src, dst, el, er, mkey, E);
        edge_sum_kernel<<<edge_blocks, 256>>>(src, dst, el, er, mkey, sbuf, E);
        edge_agg_kernel<160, 40><<<agg_blocks, 256>>>(src, dst, el, er, mkey, sbuf, z, buf, E);
    }
    // ---------------- epilogue ----------------
    final_kernel<<<(n * 40 + 255) / 256, 256>>>(buf, bias_last, (float*)d_out, n);
}

// round 2
// speedup vs baseline: 1.7232x; 1.7232x over previous
#include <cuda_runtime.h>

// ---------------------------------------------------------------------------
// GAT: 3 layers, N=50000, E=800000, IN=128, H=4, D=32, C=40
// R2: dst-CSR built once per launch; per-layer fused node-softmax+aggregate
//     (warp per dst node, zero atomics in the hot path). GEMM: 64 rows/block,
//     8 rows/thread, packed f32x2 FMA.
// ---------------------------------------------------------------------------

#define NMAX 50000
#define EMAX 800000
#define SLOPE 0.2f
#define BN_EPS 1e-5f
#define NEG_INF (-1e30f)

// ---------------- scratch ----------------
__device__ __align__(16) float g_z  [NMAX * 160];
__device__ __align__(16) float g_buf[NMAX * 160];
__device__ __align__(16) float g_h  [NMAX * 128];
__device__ __align__(16) float g_el [NMAX * 4];
__device__ __align__(16) float g_er [NMAX * 4];
__device__ __align__(16) float g_bnsum[256];
__device__ int g_deg[NMAX];
__device__ int g_rowptr[NMAX + 1];
__device__ int g_wcur[NMAX];
__device__ int g_csrsrc[EMAX];

// ---------------- helpers ----------------
__device__ __forceinline__ unsigned long long pack2(float a, float b) {
    unsigned long long r;
    asm("mov.b64 %0, {%1, %2};" : "=l"(r) : "f"(a), "f"(b));
    return r;
}
__device__ __forceinline__ void fma2(unsigned long long& acc, unsigned long long a,
                                     unsigned long long b) {
    asm("fma.rn.f32x2 %0, %1, %2, %0;" : "+l"(acc) : "l"(a), "l"(b));
}
__device__ __forceinline__ float2 unpack2(unsigned long long v) {
    float2 f;
    asm("mov.b64 {%0, %1}, %2;" : "=f"(f.x), "=f"(f.y) : "l"(v));
    return f;
}
__device__ __forceinline__ float lrelu(float x) { return x >= 0.f ? x : SLOPE * x; }

// ================= CSR build =================
__global__ void zero_deg_kernel(int* __restrict__ deg, int n) {
    int i = blockIdx.x * blockDim.x + threadIdx.x;
    if (i < n) deg[i] = 0;
}
__global__ void count_kernel(const int* __restrict__ dst, int* __restrict__ deg, int E) {
    int e = blockIdx.x * blockDim.x + threadIdx.x;
    if (e < E) atomicAdd(&deg[dst[e]], 1);
}
// single-block exclusive scan over n counters
__global__ void scan_kernel(const int* __restrict__ deg, int* __restrict__ rowptr,
                            int* __restrict__ wcur, int n) {
    __shared__ int sdata[1024];
    __shared__ int carry_s;
    int tid = threadIdx.x;
    if (tid == 0) carry_s = 0;
    __syncthreads();
    for (int base = 0; base < n; base += 1024) {
        int i = base + tid;
        int v = (i < n) ? deg[i] : 0;
        sdata[tid] = v;
        __syncthreads();
        for (int off = 1; off < 1024; off <<= 1) {
            int t = (tid >= off) ? sdata[tid - off] : 0;
            __syncthreads();
            sdata[tid] += t;
            __syncthreads();
        }
        int c = carry_s;
        int excl = c + sdata[tid] - v;
        if (i < n) {
            rowptr[i] = excl;
            wcur[i] = excl;
        }
        __syncthreads();
        if (tid == 1023) carry_s = c + sdata[1023];
        __syncthreads();
    }
    if (tid == 0) rowptr[n] = carry_s;
}
__global__ void scatter_kernel(const int* __restrict__ src, const int* __restrict__ dst,
                               int* __restrict__ wcur, int* __restrict__ csrsrc, int E) {
    int e = blockIdx.x * blockDim.x + threadIdx.x;
    if (e < E) {
        int pos = atomicAdd(&wcur[dst[e]], 1);
        csrsrc[pos] = src[e];
    }
}

// ================= GEMM: out[n,KOUT] = X[n,128] @ W[128,KOUT] (+bias) ========
// block (KOUT/4, 8), 64 rows/block, 8 rows/thread.
template <int KOUT>
__global__ void gemm_kernel(const float* __restrict__ X, const float* __restrict__ W,
                            const float* __restrict__ bias, float* __restrict__ out,
                            int n) {
    __shared__ __align__(16) float xs[64][32];
    __shared__ __align__(16) float ws[32][KOUT];
    const int tx = threadIdx.x;                // 0..KOUT/4-1
    const int ty = threadIdx.y;                // 0..7
    const int nth = 8 * (KOUT / 4);
    const int tid = ty * (KOUT / 4) + tx;
    const int row0 = blockIdx.x * 64;

    unsigned long long acc[8][2] = {};

    for (int k0 = 0; k0 < 128; k0 += 32) {
        // X tile: 64x32 = 512 float4
        for (int i = tid; i < 512; i += nth) {
            int r = i >> 3, c4 = i & 7;
            int gr = row0 + r;
            float4 v = (gr < n) ? *(const float4*)&X[gr * 128 + k0 + c4 * 4]
                                : make_float4(0.f, 0.f, 0.f, 0.f);
            *(float4*)&xs[r][c4 * 4] = v;
        }
        // W tile: 32xKOUT
        for (int i = tid; i < 32 * (KOUT / 4); i += nth) {
            int r = i / (KOUT / 4), c4 = i - r * (KOUT / 4);
            *(float4*)&ws[r][c4 * 4] = *(const float4*)&W[(k0 + r) * KOUT + c4 * 4];
        }
        __syncthreads();
#pragma unroll 4
        for (int k = 0; k < 32; k++) {
            const float4 w4 = *(const float4*)&ws[k][tx * 4];
            const unsigned long long w01 = pack2(w4.x, w4.y);
            const unsigned long long w23 = pack2(w4.z, w4.w);
#pragma unroll
            for (int i = 0; i < 8; i++) {
                float xv = xs[ty * 8 + i][k];
                unsigned long long x2 = pack2(xv, xv);
                fma2(acc[i][0], x2, w01);
                fma2(acc[i][1], x2, w23);
            }
        }
        __syncthreads();
    }

    float4 bi = make_float4(0.f, 0.f, 0.f, 0.f);
    if (bias) bi = *(const float4*)&bias[tx * 4];
#pragma unroll
    for (int i = 0; i < 8; i++) {
        int r = row0 + ty * 8 + i;
        if (r < n) {
            float2 a = unpack2(acc[i][0]);
            float2 b = unpack2(acc[i][1]);
            float4 o = make_float4(a.x + bi.x, a.y + bi.y, b.x + bi.z, b.y + bi.w);
            *(float4*)&out[r * KOUT + tx * 4] = o;
        }
    }
}

// ================= el/er per (node, head) =================
template <int FOUT>
__global__ void eler_kernel(const float* __restrict__ z, const float* __restrict__ al,
                            const float* __restrict__ ar, float* __restrict__ el,
                            float* __restrict__ er, int n) {
    int idx = blockIdx.x * blockDim.x + threadIdx.x;
    if (idx >= n * 4) return;
    int h = idx & 3;
    int node = idx >> 2;
    const float* zp = z + node * (4 * FOUT) + h * FOUT;
    const float* alp = al + h * FOUT;
    const float* arp = ar + h * FOUT;
    float sl = 0.f, sr = 0.f;
#pragma unroll
    for (int d = 0; d < FOUT; d++) {
        float v = zp[d];
        sl += v * alp[d];
        sr += v * arp[d];
    }
    el[idx] = sl;
    er[idx] = sr;
}

// ================= fused softmax + aggregation: warp per dst node ============
// out[dst] += sum_e alpha_e,h * z[src_e]   (out prefilled with x@Wl + bc)
template <int KOUT, int FOUT>
__global__ void node_agg_kernel(const int* __restrict__ rowptr, const int* __restrict__ csrsrc,
                                const float* __restrict__ el, const float* __restrict__ er,
                                const float* __restrict__ z, float* __restrict__ out, int n) {
    constexpr int WARPS = 8;
    constexpr int CAP = 64;                       // cached exp() values per chunk
    constexpr int G = KOUT / 4;                   // float4 groups per row
    constexpr int GPL = (G + 31) / 32;            // groups per lane
    __shared__ __align__(16) float4 s_ex[WARPS][CAP];

    int wid = threadIdx.x >> 5;
    int lane = threadIdx.x & 31;
    int node = blockIdx.x * WARPS + wid;
    if (node >= n) return;
    int beg = rowptr[node];
    int deg = rowptr[node + 1] - beg;
    if (deg == 0) return;

    float4 erv = *(const float4*)&er[node * 4];

    // ---- phase 1: per-head max ----
    float m0 = NEG_INF, m1 = NEG_INF, m2 = NEG_INF, m3 = NEG_INF;
    for (int i = lane; i < deg; i += 32) {
        int s = __ldg(&csrsrc[beg + i]);
        float4 a = __ldg((const float4*)&el[s * 4]);
        m0 = fmaxf(m0, lrelu(a.x + erv.x));
        m1 = fmaxf(m1, lrelu(a.y + erv.y));
        m2 = fmaxf(m2, lrelu(a.z + erv.z));
        m3 = fmaxf(m3, lrelu(a.w + erv.w));
    }
#pragma unroll
    for (int off = 16; off > 0; off >>= 1) {
        m0 = fmaxf(m0, __shfl_xor_sync(0xFFFFFFFFu, m0, off));
        m1 = fmaxf(m1, __shfl_xor_sync(0xFFFFFFFFu, m1, off));
        m2 = fmaxf(m2, __shfl_xor_sync(0xFFFFFFFFu, m2, off));
        m3 = fmaxf(m3, __shfl_xor_sync(0xFFFFFFFFu, m3, off));
    }

    // ---- phase 2: per-head sum of exp ----
    float s0 = 0.f, s1 = 0.f, s2 = 0.f, s3 = 0.f;
    for (int i = lane; i < deg; i += 32) {
        int s = __ldg(&csrsrc[beg + i]);
        float4 a = __ldg((const float4*)&el[s * 4]);
        s0 += __expf(lrelu(a.x + erv.x) - m0);
        s1 += __expf(lrelu(a.y + erv.y) - m1);
        s2 += __expf(lrelu(a.z + erv.z) - m2);
        s3 += __expf(lrelu(a.w + erv.w) - m3);
    }
#pragma unroll
    for (int off = 16; off > 0; off >>= 1) {
        s0 += __shfl_xor_sync(0xFFFFFFFFu, s0, off);
        s1 += __shfl_xor_sync(0xFFFFFFFFu, s1, off);
        s2 += __shfl_xor_sync(0xFFFFFFFFu, s2, off);
        s3 += __shfl_xor_sync(0xFFFFFFFFu, s3, off);
    }
    float r0 = 1.f / s0, r1 = 1.f / s1, r2 = 1.f / s2, r3 = 1.f / s3;

    // ---- phase 3: chunked aggregation ----
    // lane's group(s): j4 = lane (+32); head of a group = (j4*4)/FOUT
    float4 acc[GPL];
#pragma unroll
    for (int g = 0; g < GPL; g++) acc[g] = make_float4(0.f, 0.f, 0.f, 0.f);

    int hsel[GPL];
#pragma unroll
    for (int g = 0; g < GPL; g++) hsel[g] = ((lane + 32 * g) * 4) / FOUT;

    for (int base = 0; base < deg; base += CAP) {
        int cnt = min(CAP, deg - base);
        // compute alpha (already divided by s) for this chunk into smem
        for (int i = lane; i < cnt; i += 32) {
            int s = __ldg(&csrsrc[beg + base + i]);
            float4 a = __ldg((const float4*)&el[s * 4]);
            float4 ex;
            ex.x = __expf(lrelu(a.x + erv.x) - m0) * r0;
            ex.y = __expf(lrelu(a.y + erv.y) - m1) * r1;
            ex.z = __expf(lrelu(a.z + erv.z) - m2) * r2;
            ex.w = __expf(lrelu(a.w + erv.w) - m3) * r3;
            s_ex[wid][i] = ex;
        }
        __syncwarp();
        for (int i = 0; i < cnt; i++) {
            int s = __ldg(&csrsrc[beg + base + i]);   // uniform -> broadcast
            float4 ex4 = s_ex[wid][i];
#pragma unroll
            for (int g = 0; g < GPL; g++) {
                int j4 = lane + 32 * g;
                if (G <= 32 || j4 < G) {
                    int h = hsel[g];
                    float a = (h == 0) ? ex4.x : (h == 1) ? ex4.y : (h == 2) ? ex4.z : ex4.w;
                    float4 zv = __ldg((const float4*)&z[s * KOUT + j4 * 4]);
                    acc[g].x += a * zv.x;
                    acc[g].y += a * zv.y;
                    acc[g].z += a * zv.z;
                    acc[g].w += a * zv.w;
                }
            }
        }
        __syncwarp();
    }

    // single non-atomic RMW (warp owns this node)
#pragma unroll
    for (int g = 0; g < GPL; g++) {
        int j4 = lane + 32 * g;
        if (G <= 32 || j4 < G) {
            float4 o = *(float4*)&out[node * KOUT + j4 * 4];
            o.x += acc[g].x;
            o.y += acc[g].y;
            o.z += acc[g].z;
            o.w += acc[g].w;
            *(float4*)&out[node * KOUT + j4 * 4] = o;
        }
    }
}

// ================= BatchNorm + ReLU =================
__global__ void bn_init_kernel(float* __restrict__ sums) { sums[threadIdx.x] = 0.f; }

__global__ void bn_reduce_kernel(const float* __restrict__ x, float* __restrict__ sums,
                                 int n) {
    int c = threadIdx.x;  // 128 columns
    int r0 = blockIdx.x * 256;
    int r1 = min(r0 + 256, n);
    float s = 0.f, s2 = 0.f;
    for (int r = r0; r < r1; r++) {
        float v = x[r * 128 + c];
        s += v;
        s2 += v * v;
    }
    atomicAdd(&sums[c], s);
    atomicAdd(&sums[128 + c], s2);
}

__global__ void bn_apply_kernel(const float* __restrict__ x, const float* __restrict__ sums,
                                const float* __restrict__ g, const float* __restrict__ b,
                                float* __restrict__ out, int n) {
    int idx = blockIdx.x * blockDim.x + threadIdx.x;
    if (idx >= n * 128) return;
    int c = idx & 127;
    float inv_n = 1.f / (float)n;
    float mean = sums[c] * inv_n;
    float var = sums[128 + c] * inv_n - mean * mean;
    float y = (x[idx] - mean) * rsqrtf(var + BN_EPS) * g[c] + b[c];
    out[idx] = y > 0.f ? y : 0.f;
}

// ================= final: mean over heads + bias =================
__global__ void final_kernel(const float* __restrict__ buf, const float* __restrict__ bias,
                             float* __restrict__ out, int n) {
    int idx = blockIdx.x * blockDim.x + threadIdx.x;
    if (idx >= n * 40) return;
    int node = idx / 40;
    int c = idx - node * 40;
    const float* p = buf + node * 160;
    out[idx] = 0.25f * (p[c] + p[40 + c] + p[80 + c] + p[120 + c]) + bias[c];
}

// ---------------------------------------------------------------------------
extern "C" void kernel_launch(void* const* d_in, const int* in_sizes, int n_in,
                              void* d_out, int out_size) {
    const float* feat = (const float*)d_in[0];
    const int* src = (const int*)d_in[1];
    const int* dst = (const int*)d_in[2];
    const float* Wc0 = (const float*)d_in[3];
    const float* al0 = (const float*)d_in[4];
    const float* ar0 = (const float*)d_in[5];
    const float* bc0 = (const float*)d_in[6];
    const float* Wl0 = (const float*)d_in[7];
    const float* Wc1 = (const float*)d_in[8];
    const float* al1 = (const float*)d_in[9];
    const float* ar1 = (const float*)d_in[10];
    const float* bc1 = (const float*)d_in[11];
    const float* Wl1 = (const float*)d_in[12];
    const float* Wc2 = (const float*)d_in[13];
    const float* al2 = (const float*)d_in[14];
    const float* ar2 = (const float*)d_in[15];
    const float* bc2 = (const float*)d_in[16];
    const float* Wl2 = (const float*)d_in[17];
    const float* g0 = (const float*)d_in[18];
    const float* b0 = (const float*)d_in[19];
    const float* g1 = (const float*)d_in[20];
    const float* b1 = (const float*)d_in[21];
    const float* bias_last = (const float*)d_in[22];

    const int n = in_sizes[0] / 128;  // 50000
    const int E = in_sizes[1];        // 800000

    float *z, *buf, *hbuf, *el, *er, *bnsum;
    int *deg, *rowptr, *wcur, *csrsrc;
    cudaGetSymbolAddress((void**)&z, g_z);
    cudaGetSymbolAddress((void**)&buf, g_buf);
    cudaGetSymbolAddress((void**)&hbuf, g_h);
    cudaGetSymbolAddress((void**)&el, g_el);
    cudaGetSymbolAddress((void**)&er, g_er);
    cudaGetSymbolAddress((void**)&bnsum, g_bnsum);
    cudaGetSymbolAddress((void**)&deg, g_deg);
    cudaGetSymbolAddress((void**)&rowptr, g_rowptr);
    cudaGetSymbolAddress((void**)&wcur, g_wcur);
    cudaGetSymbolAddress((void**)&csrsrc, g_csrsrc);

    const int gemm_blocks = (n + 63) / 64;
    const int edge_blocks = (E + 255) / 256;
    const int agg_blocks = (n + 7) / 8;

    // ---- CSR build (graph shared by all 3 layers) ----
    zero_deg_kernel<<<(n + 255) / 256, 256>>>(deg, n);
    count_kernel<<<edge_blocks, 256>>>(dst, deg, E);
    scan_kernel<<<1, 1024>>>(deg, rowptr, wcur, n);
    scatter_kernel<<<edge_blocks, 256>>>(src, dst, wcur, csrsrc, E);

    // ---- layer 0 ----
    {
        dim3 b(32, 8);
        gemm_kernel<128><<<gemm_blocks, b>>>(feat, Wc0, nullptr, z, n);
        gemm_kernel<128><<<gemm_blocks, b>>>(feat, Wl0, bc0, buf, n);
        eler_kernel<32><<<(n * 4 + 255) / 256, 256>>>(z, al0, ar0, el, er, n);
        node_agg_kernel<128, 32><<<agg_blocks, 256>>>(rowptr, csrsrc, el, er, z, buf, n);
        bn_init_kernel<<<1, 256>>>(bnsum);
        bn_reduce_kernel<<<(n + 255) / 256, 128>>>(buf, bnsum, n);
        bn_apply_kernel<<<(n * 128 + 255) / 256, 256>>>(buf, bnsum, g0, b0, hbuf, n);
    }
    // ---- layer 1 ----
    {
        dim3 b(32, 8);
        gemm_kernel<128><<<gemm_blocks, b>>>(hbuf, Wc1, nullptr, z, n);
        gemm_kernel<128><<<gemm_blocks, b>>>(hbuf, Wl1, bc1, buf, n);
        eler_kernel<32><<<(n * 4 + 255) / 256, 256>>>(z, al1, ar1, el, er, n);
        node_agg_kernel<128, 32><<<agg_blocks, 256>>>(rowptr, csrsrc, el, er, z, buf, n);
        bn_init_kernel<<<1, 256>>>(bnsum);
        bn_reduce_kernel<<<(n + 255) / 256, 128>>>(buf, bnsum, n);
        bn_apply_kernel<<<(n * 128 + 255) / 256, 256>>>(buf, bnsum, g1, b1, hbuf, n);
    }
    // ---- layer 2 ----
    {
        dim3 b(40, 8);
        gemm_kernel<160><<<gemm_blocks, b>>>(hbuf, Wc2, nullptr, z, n);
        gemm_kernel<160><<<gemm_blocks, b>>>(hbuf, Wl2, bc2, buf, n);
        eler_kernel<40><<<(n * 4 + 255) / 256, 256>>>(z, al2, ar2, el, er, n);
        node_agg_kernel<160, 40><<<agg_blocks, 256>>>(rowptr, csrsrc, el, er, z, buf, n);
    }
    // ---- epilogue ----
    final_kernel<<<(n * 40 + 255) / 256, 256>>>(buf, bias_last, (float*)d_out, n);
}

// round 4
// speedup vs baseline: 1.8573x; 1.0778x over previous
#include <cuda_runtime.h>
#include <cuda_bf16.h>
#include <cstdint>

// ---------------------------------------------------------------------------
// GAT: 3 layers, N=50000, E=800000, IN=128, H=4, D=32, C=40
// R4: GEMMs via mma.sync m16n8k16 bf16 (split-bf16, 3 products, fp32 acc).
//     tcgen05 unavailable (harness targets compute_103 PTX). Rest = R2:
//     CSR softmax+agg (atomic-free), BN, eler, final.
// ---------------------------------------------------------------------------

#define NMAX 50000
#define EMAX 800000
#define SLOPE 0.2f
#define BN_EPS 1e-5f
#define NEG_INF (-1e30f)

// ---------------- scratch ----------------
__device__ __align__(16) float g_z  [NMAX * 160];
__device__ __align__(16) float g_buf[NMAX * 160];
__device__ __align__(16) float g_h  [NMAX * 128];
__device__ __align__(16) float g_el [NMAX * 4];
__device__ __align__(16) float g_er [NMAX * 4];
__device__ __align__(16) float g_bnsum[256];
__device__ int g_deg[NMAX];
__device__ int g_rowptr[NMAX + 1];
__device__ int g_wcur[NMAX];
__device__ int g_csrsrc[EMAX];
// transposed weights [layer*2 + (c=0/l=1)], N-major [N][K=128], split hi/lo
__device__ __align__(16) __nv_bfloat16 g_wthi[6][160 * 128];
__device__ __align__(16) __nv_bfloat16 g_wtlo[6][160 * 128];

__device__ __forceinline__ uint32_t smem_u32(const void* p) {
    uint32_t a;
    asm("{ .reg .u64 t; cvta.to.shared.u64 t, %1; cvt.u32.u64 %0, t; }" : "=r"(a) : "l"(p));
    return a;
}
__device__ __forceinline__ float lrelu(float x) { return x >= 0.f ? x : SLOPE * x; }

__device__ __forceinline__ void ldmx4(uint32_t* r, uint32_t addr) {
    asm volatile("ldmatrix.sync.aligned.m8n8.x4.shared.b16 {%0,%1,%2,%3}, [%4];"
                 : "=r"(r[0]), "=r"(r[1]), "=r"(r[2]), "=r"(r[3]) : "r"(addr));
}
__device__ __forceinline__ void ldmx2(uint32_t* r, uint32_t addr) {
    asm volatile("ldmatrix.sync.aligned.m8n8.x2.shared.b16 {%0,%1}, [%2];"
                 : "=r"(r[0]), "=r"(r[1]) : "r"(addr));
}
__device__ __forceinline__ void mma16816(float* c, const uint32_t* a, const uint32_t* b) {
    asm volatile(
        "mma.sync.aligned.m16n8k16.row.col.f32.bf16.bf16.f32 "
        "{%0,%1,%2,%3}, {%4,%5,%6,%7}, {%8,%9}, {%0,%1,%2,%3};"
        : "+f"(c[0]), "+f"(c[1]), "+f"(c[2]), "+f"(c[3])
        : "r"(a[0]), "r"(a[1]), "r"(a[2]), "r"(a[3]), "r"(b[0]), "r"(b[1]));
}

// ================= weight transpose + split =================
__global__ void wsplit_kernel(const float* __restrict__ W, __nv_bfloat16* __restrict__ hi,
                              __nv_bfloat16* __restrict__ lo, int N, int K) {
    int i = blockIdx.x * blockDim.x + threadIdx.x;
    if (i < N * K) {
        int nn = i / K, kk = i - nn * K;
        float v = W[kk * N + nn];
        __nv_bfloat16 h = __float2bfloat16(v);
        hi[i] = h;
        lo[i] = __float2bfloat16(v - __bfloat162float(h));
    }
}

// ================= mma.sync GEMM =================
// out[n,N] = X[n,128] @ W[128,N] (+bias). BM=128, K=128 resident, 8 warps (4x2).
// Split-bf16: Ah*Bh + Ah*Bl + Al*Bh, fp32 accum. X converted to hi/lo in-kernel.
template <int N, bool BIAS>
__global__ void __launch_bounds__(256, 1)
gemm_mma(const float* __restrict__ X, const __nv_bfloat16* __restrict__ Bhi,
         const __nv_bfloat16* __restrict__ Blo, const float* __restrict__ bias,
         float* __restrict__ out, int n) {
    constexpr int LDA = 136;          // padded row (272B: conflict-free ldmatrix)
    constexpr int NF = N / 16;        // n-frags per warp (warp n-tile = N/2)
    extern __shared__ __align__(16) char smem[];
    __nv_bfloat16* sAh = (__nv_bfloat16*)smem;
    __nv_bfloat16* sAl = sAh + 128 * LDA;
    __nv_bfloat16* sBh = sAl + 128 * LDA;
    __nv_bfloat16* sBl = sBh + N * LDA;

    const int tid = threadIdx.x;
    const int wid = tid >> 5;
    const int lane = tid & 31;
    const int wm = wid & 3;           // warp row (4)
    const int wn = wid >> 2;          // warp col (2)
    const int row0 = blockIdx.x * 128;

    // ---- fill A (convert fp32 -> bf16 hi/lo) ----
    for (int idx = tid; idx < 128 * 32; idx += 256) {
        int r = idx >> 5, c4 = idx & 31;
        int gr = row0 + r;
        float4 v = make_float4(0.f, 0.f, 0.f, 0.f);
        if (gr < n) v = *(const float4*)&X[gr * 128 + c4 * 4];
        __nv_bfloat162 h01, h23, l01, l23;
        h01.x = __float2bfloat16(v.x); l01.x = __float2bfloat16(v.x - __bfloat162float(h01.x));
        h01.y = __float2bfloat16(v.y); l01.y = __float2bfloat16(v.y - __bfloat162float(h01.y));
        h23.x = __float2bfloat16(v.z); l23.x = __float2bfloat16(v.z - __bfloat162float(h23.x));
        h23.y = __float2bfloat16(v.w); l23.y = __float2bfloat16(v.w - __bfloat162float(h23.y));
        uint2 hu, lu;
        hu.x = *(uint32_t*)&h01; hu.y = *(uint32_t*)&h23;
        lu.x = *(uint32_t*)&l01; lu.y = *(uint32_t*)&l23;
        *(uint2*)&sAh[r * LDA + c4 * 4] = hu;
        *(uint2*)&sAl[r * LDA + c4 * 4] = lu;
    }
    // ---- fill B (already split, [N][128] bf16) ----
    for (int idx = tid; idx < N * 16; idx += 256) {
        int r = idx >> 4, c = idx & 15;
        *(uint4*)&sBh[r * LDA + c * 8] = *(const uint4*)&Bhi[r * 128 + c * 8];
        *(uint4*)&sBl[r * LDA + c * 8] = *(const uint4*)&Blo[r * 128 + c * 8];
    }
    __syncthreads();

    const uint32_t uAh = smem_u32(sAh), uAl = smem_u32(sAl);
    const uint32_t uBh = smem_u32(sBh), uBl = smem_u32(sBl);

    // lane-invariant address pieces
    const int arow = wm * 32 + (lane & 15);
    const int acol8 = (lane >> 4) * 8;
    const int brow = wn * (N / 2) + (lane & 7);
    const int bcol8 = ((lane >> 3) & 1) * 8;

    float c[2][NF][4];
#pragma unroll
    for (int i = 0; i < 2; i++)
#pragma unroll
        for (int j = 0; j < NF; j++)
#pragma unroll
            for (int k = 0; k < 4; k++) c[i][j][k] = 0.f;

#pragma unroll
    for (int split = 0; split < 3; split++) {
        const uint32_t aB = (split == 2) ? uAl : uAh;
        const uint32_t bB = (split == 1) ? uBl : uBh;
#pragma unroll
        for (int ks = 0; ks < 8; ks++) {
            uint32_t a[2][4];
#pragma unroll
            for (int i = 0; i < 2; i++)
                ldmx4(a[i], aB + (uint32_t)(((arow + i * 16) * LDA + ks * 16 + acol8) * 2));
            uint32_t b[NF][2];
#pragma unroll
            for (int j = 0; j < NF; j++)
                ldmx2(b[j], bB + (uint32_t)(((brow + j * 8) * LDA + ks * 16 + bcol8) * 2));
#pragma unroll
            for (int i = 0; i < 2; i++)
#pragma unroll
                for (int j = 0; j < NF; j++) mma16816(c[i][j], a[i], b[j]);
        }
    }

    // ---- store ----
    const int quad = lane >> 2, tq = lane & 3;
#pragma unroll
    for (int i = 0; i < 2; i++) {
#pragma unroll
        for (int half = 0; half < 2; half++) {
            int r = row0 + wm * 32 + i * 16 + quad + half * 8;
            if (r < n) {
#pragma unroll
                for (int j = 0; j < NF; j++) {
                    int col = wn * (N / 2) + j * 8 + tq * 2;
                    float2 v = make_float2(c[i][j][half * 2], c[i][j][half * 2 + 1]);
                    if (BIAS) {
                        v.x += __ldg(&bias[col]);
                        v.y += __ldg(&bias[col + 1]);
                    }
                    *(float2*)&out[r * N + col] = v;
                }
            }
        }
    }
}

// ================= el/er per (node, head) =================
template <int FOUT>
__global__ void eler_kernel(const float* __restrict__ z, const float* __restrict__ al,
                            const float* __restrict__ ar, float* __restrict__ el,
                            float* __restrict__ er, int n) {
    int idx = blockIdx.x * blockDim.x + threadIdx.x;
    if (idx >= n * 4) return;
    int h = idx & 3;
    int node = idx >> 2;
    const float* zp = z + node * (4 * FOUT) + h * FOUT;
    const float* alp = al + h * FOUT;
    const float* arp = ar + h * FOUT;
    float sl = 0.f, sr = 0.f;
#pragma unroll
    for (int d = 0; d < FOUT; d++) {
        float v = zp[d];
        sl += v * alp[d];
        sr += v * arp[d];
    }
    el[idx] = sl;
    er[idx] = sr;
}

// ================= CSR build =================
__global__ void zero_deg_kernel(int* __restrict__ deg, int n) {
    int i = blockIdx.x * blockDim.x + threadIdx.x;
    if (i < n) deg[i] = 0;
}
__global__ void count_kernel(const int* __restrict__ dst, int* __restrict__ deg, int E) {
    int e = blockIdx.x * blockDim.x + threadIdx.x;
    if (e < E) atomicAdd(&deg[dst[e]], 1);
}
__global__ void scan_kernel(const int* __restrict__ deg, int* __restrict__ rowptr,
                            int* __restrict__ wcur, int n) {
    __shared__ int sdata[1024];
    __shared__ int carry_s;
    int tid = threadIdx.x;
    if (tid == 0) carry_s = 0;
    __syncthreads();
    for (int base = 0; base < n; base += 1024) {
        int i = base + tid;
        int v = (i < n) ? deg[i] : 0;
        sdata[tid] = v;
        __syncthreads();
        for (int off = 1; off < 1024; off <<= 1) {
            int t = (tid >= off) ? sdata[tid - off] : 0;
            __syncthreads();
            sdata[tid] += t;
            __syncthreads();
        }
        int c = carry_s;
        int excl = c + sdata[tid] - v;
        if (i < n) { rowptr[i] = excl; wcur[i] = excl; }
        __syncthreads();
        if (tid == 1023) carry_s = c + sdata[1023];
        __syncthreads();
    }
    if (tid == 0) rowptr[n] = carry_s;
}
__global__ void scatter_kernel(const int* __restrict__ src, const int* __restrict__ dst,
                               int* __restrict__ wcur, int* __restrict__ csrsrc, int E) {
    int e = blockIdx.x * blockDim.x + threadIdx.x;
    if (e < E) {
        int pos = atomicAdd(&wcur[dst[e]], 1);
        csrsrc[pos] = src[e];
    }
}

// ================= fused softmax + aggregation: warp per dst node ============
template <int KOUT, int FOUT>
__global__ void node_agg_kernel(const int* __restrict__ rowptr, const int* __restrict__ csrsrc,
                                const float* __restrict__ el, const float* __restrict__ er,
                                const float* __restrict__ z, float* __restrict__ out, int n) {
    constexpr int WARPS = 8;
    constexpr int CAP = 64;
    constexpr int G = KOUT / 4;
    constexpr int GPL = (G + 31) / 32;
    __shared__ __align__(16) float4 s_ex[WARPS][CAP];

    int wid = threadIdx.x >> 5;
    int lane = threadIdx.x & 31;
    int node = blockIdx.x * WARPS + wid;
    if (node >= n) return;
    int beg = rowptr[node];
    int deg = rowptr[node + 1] - beg;
    if (deg == 0) return;

    float4 erv = *(const float4*)&er[node * 4];

    float m0 = NEG_INF, m1 = NEG_INF, m2 = NEG_INF, m3 = NEG_INF;
    for (int i = lane; i < deg; i += 32) {
        int s = __ldg(&csrsrc[beg + i]);
        float4 a = __ldg((const float4*)&el[s * 4]);
        m0 = fmaxf(m0, lrelu(a.x + erv.x));
        m1 = fmaxf(m1, lrelu(a.y + erv.y));
        m2 = fmaxf(m2, lrelu(a.z + erv.z));
        m3 = fmaxf(m3, lrelu(a.w + erv.w));
    }
#pragma unroll
    for (int off = 16; off > 0; off >>= 1) {
        m0 = fmaxf(m0, __shfl_xor_sync(0xFFFFFFFFu, m0, off));
        m1 = fmaxf(m1, __shfl_xor_sync(0xFFFFFFFFu, m1, off));
        m2 = fmaxf(m2, __shfl_xor_sync(0xFFFFFFFFu, m2, off));
        m3 = fmaxf(m3, __shfl_xor_sync(0xFFFFFFFFu, m3, off));
    }

    float s0 = 0.f, s1 = 0.f, s2 = 0.f, s3 = 0.f;
    for (int i = lane; i < deg; i += 32) {
        int s = __ldg(&csrsrc[beg + i]);
        float4 a = __ldg((const float4*)&el[s * 4]);
        s0 += __expf(lrelu(a.x + erv.x) - m0);
        s1 += __expf(lrelu(a.y + erv.y) - m1);
        s2 += __expf(lrelu(a.z + erv.z) - m2);
        s3 += __expf(lrelu(a.w + erv.w) - m3);
    }
#pragma unroll
    for (int off = 16; off > 0; off >>= 1) {
        s0 += __shfl_xor_sync(0xFFFFFFFFu, s0, off);
        s1 += __shfl_xor_sync(0xFFFFFFFFu, s1, off);
        s2 += __shfl_xor_sync(0xFFFFFFFFu, s2, off);
        s3 += __shfl_xor_sync(0xFFFFFFFFu, s3, off);
    }
    float r0 = 1.f / s0, r1 = 1.f / s1, r2 = 1.f / s2, r3 = 1.f / s3;

    float4 acc[GPL];
#pragma unroll
    for (int g = 0; g < GPL; g++) acc[g] = make_float4(0.f, 0.f, 0.f, 0.f);
    int hsel[GPL];
#pragma unroll
    for (int g = 0; g < GPL; g++) hsel[g] = ((lane + 32 * g) * 4) / FOUT;

    for (int base = 0; base < deg; base += CAP) {
        int cnt = min(CAP, deg - base);
        for (int i = lane; i < cnt; i += 32) {
            int s = __ldg(&csrsrc[beg + base + i]);
            float4 a = __ldg((const float4*)&el[s * 4]);
            float4 ex;
            ex.x = __expf(lrelu(a.x + erv.x) - m0) * r0;
            ex.y = __expf(lrelu(a.y + erv.y) - m1) * r1;
            ex.z = __expf(lrelu(a.z + erv.z) - m2) * r2;
            ex.w = __expf(lrelu(a.w + erv.w) - m3) * r3;
            s_ex[wid][i] = ex;
        }
        __syncwarp();
        for (int i = 0; i < cnt; i++) {
            int s = __ldg(&csrsrc[beg + base + i]);
            float4 ex4 = s_ex[wid][i];
#pragma unroll
            for (int g = 0; g < GPL; g++) {
                int j4 = lane + 32 * g;
                if (G <= 32 || j4 < G) {
                    int h = hsel[g];
                    float a = (h == 0) ? ex4.x : (h == 1) ? ex4.y : (h == 2) ? ex4.z : ex4.w;
                    float4 zv = __ldg((const float4*)&z[s * KOUT + j4 * 4]);
                    acc[g].x += a * zv.x;
                    acc[g].y += a * zv.y;
                    acc[g].z += a * zv.z;
                    acc[g].w += a * zv.w;
                }
            }
        }
        __syncwarp();
    }

#pragma unroll
    for (int g = 0; g < GPL; g++) {
        int j4 = lane + 32 * g;
        if (G <= 32 || j4 < G) {
            float4 o = *(float4*)&out[node * KOUT + j4 * 4];
            o.x += acc[g].x;
            o.y += acc[g].y;
            o.z += acc[g].z;
            o.w += acc[g].w;
            *(float4*)&out[node * KOUT + j4 * 4] = o;
        }
    }
}

// ================= BatchNorm + ReLU =================
__global__ void bn_init_kernel(float* __restrict__ sums) { sums[threadIdx.x] = 0.f; }

__global__ void bn_reduce_kernel(const float* __restrict__ x, float* __restrict__ sums,
                                 int n) {
    int c = threadIdx.x;
    int r0 = blockIdx.x * 256;
    int r1 = min(r0 + 256, n);
    float s = 0.f, s2 = 0.f;
    for (int r = r0; r < r1; r++) {
        float v = x[r * 128 + c];
        s += v;
        s2 += v * v;
    }
    atomicAdd(&sums[c], s);
    atomicAdd(&sums[128 + c], s2);
}

__global__ void bn_apply_kernel(const float* __restrict__ x, const float* __restrict__ sums,
                                const float* __restrict__ g, const float* __restrict__ b,
                                float* __restrict__ out, int n) {
    int idx = blockIdx.x * blockDim.x + threadIdx.x;
    if (idx >= n * 128) return;
    int c = idx & 127;
    float inv_n = 1.f / (float)n;
    float mean = sums[c] * inv_n;
    float var = sums[128 + c] * inv_n - mean * mean;
    float y = (x[idx] - mean) * rsqrtf(var + BN_EPS) * g[c] + b[c];
    out[idx] = y > 0.f ? y : 0.f;
}

// ================= final: mean over heads + bias =================
__global__ void final_kernel(const float* __restrict__ buf, const float* __restrict__ bias,
                             float* __restrict__ out, int n) {
    int idx = blockIdx.x * blockDim.x + threadIdx.x;
    if (idx >= n * 40) return;
    int node = idx / 40;
    int c = idx - node * 40;
    const float* p = buf + node * 160;
    out[idx] = 0.25f * (p[c] + p[40 + c] + p[80 + c] + p[120 + c]) + bias[c];
}

// ---------------------------------------------------------------------------
extern "C" void kernel_launch(void* const* d_in, const int* in_sizes, int n_in,
                              void* d_out, int out_size) {
    const float* feat = (const float*)d_in[0];
    const int* src = (const int*)d_in[1];
    const int* dst = (const int*)d_in[2];
    const float* Wc[3] = {(const float*)d_in[3], (const float*)d_in[8], (const float*)d_in[13]};
    const float* al[3] = {(const float*)d_in[4], (const float*)d_in[9], (const float*)d_in[14]};
    const float* ar[3] = {(const float*)d_in[5], (const float*)d_in[10], (const float*)d_in[15]};
    const float* bc[3] = {(const float*)d_in[6], (const float*)d_in[11], (const float*)d_in[16]};
    const float* Wl[3] = {(const float*)d_in[7], (const float*)d_in[12], (const float*)d_in[17]};
    const float* g0 = (const float*)d_in[18];
    const float* b0 = (const float*)d_in[19];
    const float* g1 = (const float*)d_in[20];
    const float* b1 = (const float*)d_in[21];
    const float* bias_last = (const float*)d_in[22];

    const int n = in_sizes[0] / 128;  // 50000
    const int E = in_sizes[1];        // 800000

    float *z, *buf, *hbuf, *el, *er, *bnsum;
    int *deg, *rowptr, *wcur, *csrsrc;
    __nv_bfloat16 *wthi, *wtlo;
    cudaGetSymbolAddress((void**)&z, g_z);
    cudaGetSymbolAddress((void**)&buf, g_buf);
    cudaGetSymbolAddress((void**)&hbuf, g_h);
    cudaGetSymbolAddress((void**)&el, g_el);
    cudaGetSymbolAddress((void**)&er, g_er);
    cudaGetSymbolAddress((void**)&bnsum, g_bnsum);
    cudaGetSymbolAddress((void**)&deg, g_deg);
    cudaGetSymbolAddress((void**)&rowptr, g_rowptr);
    cudaGetSymbolAddress((void**)&wcur, g_wcur);
    cudaGetSymbolAddress((void**)&csrsrc, g_csrsrc);
    cudaGetSymbolAddress((void**)&wthi, g_wthi);
    cudaGetSymbolAddress((void**)&wtlo, g_wtlo);
    const int WS = 160 * 128;

    const int edge_blocks = (E + 255) / 256;
    const int agg_blocks = (n + 7) / 8;
    const int gemm_grid = (n + 127) / 128;

    const int smem128 = (256 + 256) * 136 * 2;  // 139264
    const int smem160 = (256 + 320) * 136 * 2;  // 156672
    cudaFuncSetAttribute(gemm_mma<128, false>, cudaFuncAttributeMaxDynamicSharedMemorySize, smem128);
    cudaFuncSetAttribute(gemm_mma<128, true>, cudaFuncAttributeMaxDynamicSharedMemorySize, smem128);
    cudaFuncSetAttribute(gemm_mma<160, false>, cudaFuncAttributeMaxDynamicSharedMemorySize, smem160);
    cudaFuncSetAttribute(gemm_mma<160, true>, cudaFuncAttributeMaxDynamicSharedMemorySize, smem160);

    // ---- CSR build ----
    zero_deg_kernel<<<(n + 255) / 256, 256>>>(deg, n);
    count_kernel<<<edge_blocks, 256>>>(dst, deg, E);
    scan_kernel<<<1, 1024>>>(deg, rowptr, wcur, n);
    scatter_kernel<<<edge_blocks, 256>>>(src, dst, wcur, csrsrc, E);

    // ---- weight transpose + split ----
    const int Nk[3] = {128, 128, 160};
    for (int L = 0; L < 3; L++) {
        int NN = Nk[L], cnt = NN * 128;
        wsplit_kernel<<<(cnt + 255) / 256, 256>>>(Wc[L], wthi + (L * 2 + 0) * WS,
                                                  wtlo + (L * 2 + 0) * WS, NN, 128);
        wsplit_kernel<<<(cnt + 255) / 256, 256>>>(Wl[L], wthi + (L * 2 + 1) * WS,
                                                  wtlo + (L * 2 + 1) * WS, NN, 128);
    }

    // ---- layer 0 ----
    gemm_mma<128, false><<<gemm_grid, 256, smem128>>>(feat, wthi + 0 * WS, wtlo + 0 * WS,
                                                      nullptr, z, n);
    gemm_mma<128, true><<<gemm_grid, 256, smem128>>>(feat, wthi + 1 * WS, wtlo + 1 * WS,
                                                     bc[0], buf, n);
    eler_kernel<32><<<(n * 4 + 255) / 256, 256>>>(z, al[0], ar[0], el, er, n);
    node_agg_kernel<128, 32><<<agg_blocks, 256>>>(rowptr, csrsrc, el, er, z, buf, n);
    bn_init_kernel<<<1, 256>>>(bnsum);
    bn_reduce_kernel<<<(n + 255) / 256, 128>>>(buf, bnsum, n);
    bn_apply_kernel<<<(n * 128 + 255) / 256, 256>>>(buf, bnsum, g0, b0, hbuf, n);

    // ---- layer 1 ----
    gemm_mma<128, false><<<gemm_grid, 256, smem128>>>(hbuf, wthi + 2 * WS, wtlo + 2 * WS,
                                                      nullptr, z, n);
    gemm_mma<128, true><<<gemm_grid, 256, smem128>>>(hbuf, wthi + 3 * WS, wtlo + 3 * WS,
                                                     bc[1], buf, n);
    eler_kernel<32><<<(n * 4 + 255) / 256, 256>>>(z, al[1], ar[1], el, er, n);
    node_agg_kernel<128, 32><<<agg_blocks, 256>>>(rowptr, csrsrc, el, er, z, buf, n);
    bn_init_kernel<<<1, 256>>>(bnsum);
    bn_reduce_kernel<<<(n + 255) / 256, 128>>>(buf, bnsum, n);
    bn_apply_kernel<<<(n * 128 + 255) / 256, 256>>>(buf, bnsum, g1, b1, hbuf, n);

    // ---- layer 2 ----
    gemm_mma<160, false><<<gemm_grid, 256, smem160>>>(hbuf, wthi + 4 * WS, wtlo + 4 * WS,
                                                      nullptr, z, n);
    gemm_mma<160, true><<<gemm_grid, 256, smem160>>>(hbuf, wthi + 5 * WS, wtlo + 5 * WS,
                                                     bc[2], buf, n);
    eler_kernel<40><<<(n * 4 + 255) / 256, 256>>>(z, al[2], ar[2], el, er, n);
    node_agg_kernel<160, 40><<<agg_blocks, 256>>>(rowptr, csrsrc, el, er, z, buf, n);

    // ---- epilogue ----
    final_kernel<<<(n * 40 + 255) / 256, 256>>>(buf, bias_last, (float*)d_out, n);
}

// round 6
// speedup vs baseline: 2.4755x; 1.3328x over previous
#include <cuda_runtime.h>
#include <cuda_bf16.h>
#include <cstdint>

// ---------------------------------------------------------------------------
// GAT R5 (resubmit after infra failure): parallel CSR scan; fused dual-GEMM
// per layer (mma.sync split-bf16) with el/er computed from accumulators and
// BN+ReLU fused into A-tile load; atomic-free CSR softmax+aggregation.
// ---------------------------------------------------------------------------

#define NMAX 50000
#define EMAX 800000
#define SLOPE 0.2f
#define BN_EPS 1e-5f
#define NEG_INF (-1e30f)

// ---------------- scratch ----------------
__device__ __align__(16) float g_z  [NMAX * 160];
__device__ __align__(16) float g_bufA[NMAX * 160];
__device__ __align__(16) float g_bufB[NMAX * 128];
__device__ __align__(16) float g_el [NMAX * 4];
__device__ __align__(16) float g_er [NMAX * 4];
__device__ __align__(16) float g_bnsum[256];
__device__ __align__(16) float g_bnscale[128];
__device__ __align__(16) float g_bnshift[128];
__device__ int g_deg[NMAX];
__device__ int g_rowptr[NMAX + 1];
__device__ int g_wcur[NMAX];
__device__ int g_csrsrc[EMAX];
__device__ int g_bsum[64];
// transposed weights [layer*2 + (c=0/l=1)], N-major [N][K=128], split hi/lo
__device__ __align__(16) __nv_bfloat16 g_wthi[6][160 * 128];
__device__ __align__(16) __nv_bfloat16 g_wtlo[6][160 * 128];

__device__ __forceinline__ uint32_t smem_u32(const void* p) {
    uint32_t a;
    asm("{ .reg .u64 t; cvta.to.shared.u64 t, %1; cvt.u32.u64 %0, t; }" : "=r"(a) : "l"(p));
    return a;
}
__device__ __forceinline__ float lrelu(float x) { return x >= 0.f ? x : SLOPE * x; }

__device__ __forceinline__ void ldmx4(uint32_t* r, uint32_t addr) {
    asm volatile("ldmatrix.sync.aligned.m8n8.x4.shared.b16 {%0,%1,%2,%3}, [%4];"
                 : "=r"(r[0]), "=r"(r[1]), "=r"(r[2]), "=r"(r[3]) : "r"(addr));
}
__device__ __forceinline__ void ldmx2(uint32_t* r, uint32_t addr) {
    asm volatile("ldmatrix.sync.aligned.m8n8.x2.shared.b16 {%0,%1}, [%2];"
                 : "=r"(r[0]), "=r"(r[1]) : "r"(addr));
}
__device__ __forceinline__ void mma16816(float* c, const uint32_t* a, const uint32_t* b) {
    asm volatile(
        "mma.sync.aligned.m16n8k16.row.col.f32.bf16.bf16.f32 "
        "{%0,%1,%2,%3}, {%4,%5,%6,%7}, {%8,%9}, {%0,%1,%2,%3};"
        : "+f"(c[0]), "+f"(c[1]), "+f"(c[2]), "+f"(c[3])
        : "r"(a[0]), "r"(a[1]), "r"(a[2]), "r"(a[3]), "r"(b[0]), "r"(b[1]));
}

// ================= weight transpose + split =================
__global__ void wsplit_kernel(const float* __restrict__ W, __nv_bfloat16* __restrict__ hi,
                              __nv_bfloat16* __restrict__ lo, int N, int K) {
    int i = blockIdx.x * blockDim.x + threadIdx.x;
    if (i < N * K) {
        int nn = i / K, kk = i - nn * K;
        float v = W[kk * N + nn];
        __nv_bfloat16 h = __float2bfloat16(v);
        hi[i] = h;
        lo[i] = __float2bfloat16(v - __bfloat162float(h));
    }
}

// ================= dual GEMM (mma.sync, split-bf16) =================
// Phase 1: z = X@Wc; el/er from accumulators.  Phase 2: buf = X@Wl + bc.
// BNIN: A-fill applies relu(x*scale+shift).
template <int N, int FOUT, bool BNIN>
__global__ void __launch_bounds__(256, 1)
gemm_dual(const float* __restrict__ X,
          const __nv_bfloat16* __restrict__ Bc_hi, const __nv_bfloat16* __restrict__ Bc_lo,
          const __nv_bfloat16* __restrict__ Bl_hi, const __nv_bfloat16* __restrict__ Bl_lo,
          const float* __restrict__ bcbias,
          const float* __restrict__ bnscale, const float* __restrict__ bnshift,
          float* __restrict__ z, float* __restrict__ out,
          const float* __restrict__ al, const float* __restrict__ ar,
          float* __restrict__ el, float* __restrict__ er, int n) {
    constexpr int LDA = 136;
    constexpr int NF = N / 16;
    extern __shared__ __align__(16) char smem[];
    __nv_bfloat16* sAh = (__nv_bfloat16*)smem;
    __nv_bfloat16* sAl = sAh + 128 * LDA;
    __nv_bfloat16* sBh = sAl + 128 * LDA;
    __nv_bfloat16* sBl = sBh + N * LDA;

    const int tid = threadIdx.x;
    const int wid = tid >> 5;
    const int lane = tid & 31;
    const int wm = wid & 3;
    const int wn = wid >> 2;
    const int quad = lane >> 2, tq = lane & 3;
    const int row0 = blockIdx.x * 128;

    // ---- fill A (fp32 -> bf16 hi/lo; optional BN+ReLU) ----
    for (int idx = tid; idx < 128 * 32; idx += 256) {
        int r = idx >> 5, c4 = idx & 31;
        int gr = row0 + r;
        float4 v = make_float4(0.f, 0.f, 0.f, 0.f);
        if (gr < n) {
            v = *(const float4*)&X[gr * 128 + c4 * 4];
            if (BNIN) {
                int c = c4 * 4;
                v.x = fmaxf(0.f, fmaf(v.x, __ldg(&bnscale[c + 0]), __ldg(&bnshift[c + 0])));
                v.y = fmaxf(0.f, fmaf(v.y, __ldg(&bnscale[c + 1]), __ldg(&bnshift[c + 1])));
                v.z = fmaxf(0.f, fmaf(v.z, __ldg(&bnscale[c + 2]), __ldg(&bnshift[c + 2])));
                v.w = fmaxf(0.f, fmaf(v.w, __ldg(&bnscale[c + 3]), __ldg(&bnshift[c + 3])));
            }
        }
        __nv_bfloat162 h01, h23, l01, l23;
        h01.x = __float2bfloat16(v.x); l01.x = __float2bfloat16(v.x - __bfloat162float(h01.x));
        h01.y = __float2bfloat16(v.y); l01.y = __float2bfloat16(v.y - __bfloat162float(h01.y));
        h23.x = __float2bfloat16(v.z); l23.x = __float2bfloat16(v.z - __bfloat162float(h23.x));
        h23.y = __float2bfloat16(v.w); l23.y = __float2bfloat16(v.w - __bfloat162float(h23.y));
        uint2 hu, lu;
        hu.x = *(uint32_t*)&h01; hu.y = *(uint32_t*)&h23;
        lu.x = *(uint32_t*)&l01; lu.y = *(uint32_t*)&l23;
        *(uint2*)&sAh[r * LDA + c4 * 4] = hu;
        *(uint2*)&sAl[r * LDA + c4 * 4] = lu;
    }
    // ---- fill B = Wc ----
    for (int idx = tid; idx < N * 16; idx += 256) {
        int r = idx >> 4, c = idx & 15;
        *(uint4*)&sBh[r * LDA + c * 8] = *(const uint4*)&Bc_hi[r * 128 + c * 8];
        *(uint4*)&sBl[r * LDA + c * 8] = *(const uint4*)&Bc_lo[r * 128 + c * 8];
    }
    __syncthreads();

    const uint32_t uAh = smem_u32(sAh), uAl = smem_u32(sAl);
    const uint32_t uBh = smem_u32(sBh), uBl = smem_u32(sBl);
    const int arow = wm * 32 + (lane & 15);
    const int acol8 = (lane >> 4) * 8;
    const int brow = wn * (N / 2) + (lane & 7);
    const int bcol8 = ((lane >> 3) & 1) * 8;

    float c[2][NF][4];

    // =================== PHASE 1: z = X @ Wc ===================
#pragma unroll
    for (int i = 0; i < 2; i++)
#pragma unroll
        for (int j = 0; j < NF; j++)
#pragma unroll
            for (int k = 0; k < 4; k++) c[i][j][k] = 0.f;

#pragma unroll
    for (int split = 0; split < 3; split++) {
        const uint32_t aB = (split == 2) ? uAl : uAh;
        const uint32_t bB = (split == 1) ? uBl : uBh;
#pragma unroll
        for (int ks = 0; ks < 8; ks++) {
            uint32_t a[2][4];
#pragma unroll
            for (int i = 0; i < 2; i++)
                ldmx4(a[i], aB + (uint32_t)(((arow + i * 16) * LDA + ks * 16 + acol8) * 2));
            uint32_t b[NF][2];
#pragma unroll
            for (int j = 0; j < NF; j++)
                ldmx2(b[j], bB + (uint32_t)(((brow + j * 8) * LDA + ks * 16 + bcol8) * 2));
#pragma unroll
            for (int i = 0; i < 2; i++)
#pragma unroll
                for (int j = 0; j < NF; j++) mma16816(c[i][j], a[i], b[j]);
        }
    }

    // store z + accumulate el/er partials
    float elp[4][2], erp[4][2];   // [row slot: i*2+half][head-in-warp]
#pragma unroll
    for (int s = 0; s < 4; s++) { elp[s][0] = elp[s][1] = erp[s][0] = erp[s][1] = 0.f; }

#pragma unroll
    for (int i = 0; i < 2; i++) {
#pragma unroll
        for (int half = 0; half < 2; half++) {
            int r = row0 + wm * 32 + i * 16 + quad + half * 8;
            if (r < n) {
#pragma unroll
                for (int j = 0; j < NF; j++) {
                    int col = wn * (N / 2) + j * 8 + tq * 2;
                    float v0 = c[i][j][half * 2], v1 = c[i][j][half * 2 + 1];
                    *(float2*)&z[r * N + col] = make_float2(v0, v1);
                    int hloc = (j * 8) / FOUT;
                    float a0 = __ldg(&al[col]), a1 = __ldg(&al[col + 1]);
                    float b0 = __ldg(&ar[col]), b1 = __ldg(&ar[col + 1]);
                    elp[i * 2 + half][hloc] += v0 * a0 + v1 * a1;
                    erp[i * 2 + half][hloc] += v0 * b0 + v1 * b1;
                }
            }
        }
    }
    // reduce over tq (lanes quad*4 + tq)
#pragma unroll
    for (int s = 0; s < 4; s++) {
#pragma unroll
        for (int h = 0; h < 2; h++) {
            float e = elp[s][h], f = erp[s][h];
            e += __shfl_xor_sync(0xFFFFFFFFu, e, 1);
            e += __shfl_xor_sync(0xFFFFFFFFu, e, 2);
            f += __shfl_xor_sync(0xFFFFFFFFu, f, 1);
            f += __shfl_xor_sync(0xFFFFFFFFu, f, 2);
            if (tq == 0) {
                int i = s >> 1, half = s & 1;
                int r = row0 + wm * 32 + i * 16 + quad + half * 8;
                if (r < n) {
                    int hg = wn * 2 + h;
                    el[r * 4 + hg] = e;
                    er[r * 4 + hg] = f;
                }
            }
        }
    }
    __syncthreads();   // all reads of sB done before refill

    // ---- fill B = Wl ----
    for (int idx = tid; idx < N * 16; idx += 256) {
        int r = idx >> 4, cc = idx & 15;
        *(uint4*)&sBh[r * LDA + cc * 8] = *(const uint4*)&Bl_hi[r * 128 + cc * 8];
        *(uint4*)&sBl[r * LDA + cc * 8] = *(const uint4*)&Bl_lo[r * 128 + cc * 8];
    }
    __syncthreads();

    // =================== PHASE 2: out = X @ Wl + bc ===================
#pragma unroll
    for (int i = 0; i < 2; i++)
#pragma unroll
        for (int j = 0; j < NF; j++)
#pragma unroll
            for (int k = 0; k < 4; k++) c[i][j][k] = 0.f;

#pragma unroll
    for (int split = 0; split < 3; split++) {
        const uint32_t aB = (split == 2) ? uAl : uAh;
        const uint32_t bB = (split == 1) ? uBl : uBh;
#pragma unroll
        for (int ks = 0; ks < 8; ks++) {
            uint32_t a[2][4];
#pragma unroll
            for (int i = 0; i < 2; i++)
                ldmx4(a[i], aB + (uint32_t)(((arow + i * 16) * LDA + ks * 16 + acol8) * 2));
            uint32_t b[NF][2];
#pragma unroll
            for (int j = 0; j < NF; j++)
                ldmx2(b[j], bB + (uint32_t)(((brow + j * 8) * LDA + ks * 16 + bcol8) * 2));
#pragma unroll
            for (int i = 0; i < 2; i++)
#pragma unroll
                for (int j = 0; j < NF; j++) mma16816(c[i][j], a[i], b[j]);
        }
    }

#pragma unroll
    for (int i = 0; i < 2; i++) {
#pragma unroll
        for (int half = 0; half < 2; half++) {
            int r = row0 + wm * 32 + i * 16 + quad + half * 8;
            if (r < n) {
#pragma unroll
                for (int j = 0; j < NF; j++) {
                    int col = wn * (N / 2) + j * 8 + tq * 2;
                    float2 v = make_float2(c[i][j][half * 2] + __ldg(&bcbias[col]),
                                           c[i][j][half * 2 + 1] + __ldg(&bcbias[col + 1]));
                    *(float2*)&out[r * N + col] = v;
                }
            }
        }
    }
}

// ================= CSR build (parallel scan) =================
__global__ void zero_deg_kernel(int* __restrict__ deg, int n) {
    int i = blockIdx.x * blockDim.x + threadIdx.x;
    if (i < n) deg[i] = 0;
}
__global__ void count_kernel(const int* __restrict__ dst, int* __restrict__ deg, int E) {
    int e = blockIdx.x * blockDim.x + threadIdx.x;
    if (e < E) atomicAdd(&deg[dst[e]], 1);
}
__global__ void scan_partial(const int* __restrict__ deg, int* __restrict__ rowptr,
                             int* __restrict__ bsum, int n) {
    __shared__ int sdata[1024];
    int tid = threadIdx.x;
    int i = blockIdx.x * 1024 + tid;
    int v = (i < n) ? deg[i] : 0;
    sdata[tid] = v;
    __syncthreads();
    for (int off = 1; off < 1024; off <<= 1) {
        int t = (tid >= off) ? sdata[tid - off] : 0;
        __syncthreads();
        sdata[tid] += t;
        __syncthreads();
    }
    if (i < n) rowptr[i] = sdata[tid] - v;   // local exclusive
    if (tid == 1023) bsum[blockIdx.x] = sdata[1023];
}
__global__ void scan_tops(int* __restrict__ bsum, int nb) {
    if (threadIdx.x == 0) {
        int acc = 0;
        for (int i = 0; i < nb; i++) { int t = bsum[i]; bsum[i] = acc; acc += t; }
        bsum[nb] = acc;
    }
}
__global__ void scan_add(int* __restrict__ rowptr, const int* __restrict__ bsum,
                         int* __restrict__ wcur, int n, int nb) {
    int i = blockIdx.x * 1024 + threadIdx.x;
    if (i < n) {
        int v = rowptr[i] + bsum[blockIdx.x];
        rowptr[i] = v;
        wcur[i] = v;
    }
    if (i == 0) rowptr[n] = bsum[nb];
}
__global__ void scatter_kernel(const int* __restrict__ src, const int* __restrict__ dst,
                               int* __restrict__ wcur, int* __restrict__ csrsrc, int E) {
    int e = blockIdx.x * blockDim.x + threadIdx.x;
    if (e < E) {
        int pos = atomicAdd(&wcur[dst[e]], 1);
        csrsrc[pos] = src[e];
    }
}

// ================= fused softmax + aggregation: warp per dst node ============
template <int KOUT, int FOUT>
__global__ void node_agg_kernel(const int* __restrict__ rowptr, const int* __restrict__ csrsrc,
                                const float* __restrict__ el, const float* __restrict__ er,
                                const float* __restrict__ z, float* __restrict__ out, int n) {
    constexpr int WARPS = 8;
    constexpr int CAP = 64;
    constexpr int G = KOUT / 4;
    constexpr int GPL = (G + 31) / 32;
    __shared__ __align__(16) float4 s_ex[WARPS][CAP];

    int wid = threadIdx.x >> 5;
    int lane = threadIdx.x & 31;
    int node = blockIdx.x * WARPS + wid;
    if (node >= n) return;
    int beg = rowptr[node];
    int deg = rowptr[node + 1] - beg;
    if (deg == 0) return;

    float4 erv = *(const float4*)&er[node * 4];

    float m0 = NEG_INF, m1 = NEG_INF, m2 = NEG_INF, m3 = NEG_INF;
    for (int i = lane; i < deg; i += 32) {
        int s = __ldg(&csrsrc[beg + i]);
        float4 a = __ldg((const float4*)&el[s * 4]);
        m0 = fmaxf(m0, lrelu(a.x + erv.x));
        m1 = fmaxf(m1, lrelu(a.y + erv.y));
        m2 = fmaxf(m2, lrelu(a.z + erv.z));
        m3 = fmaxf(m3, lrelu(a.w + erv.w));
    }
#pragma unroll
    for (int off = 16; off > 0; off >>= 1) {
        m0 = fmaxf(m0, __shfl_xor_sync(0xFFFFFFFFu, m0, off));
        m1 = fmaxf(m1, __shfl_xor_sync(0xFFFFFFFFu, m1, off));
        m2 = fmaxf(m2, __shfl_xor_sync(0xFFFFFFFFu, m2, off));
        m3 = fmaxf(m3, __shfl_xor_sync(0xFFFFFFFFu, m3, off));
    }

    float s0 = 0.f, s1 = 0.f, s2 = 0.f, s3 = 0.f;
    for (int i = lane; i < deg; i += 32) {
        int s = __ldg(&csrsrc[beg + i]);
        float4 a = __ldg((const float4*)&el[s * 4]);
        s0 += __expf(lrelu(a.x + erv.x) - m0);
        s1 += __expf(lrelu(a.y + erv.y) - m1);
        s2 += __expf(lrelu(a.z + erv.z) - m2);
        s3 += __expf(lrelu(a.w + erv.w) - m3);
    }
#pragma unroll
    for (int off = 16; off > 0; off >>= 1) {
        s0 += __shfl_xor_sync(0xFFFFFFFFu, s0, off);
        s1 += __shfl_xor_sync(0xFFFFFFFFu, s1, off);
        s2 += __shfl_xor_sync(0xFFFFFFFFu, s2, off);
        s3 += __shfl_xor_sync(0xFFFFFFFFu, s3, off);
    }
    float r0 = 1.f / s0, r1 = 1.f / s1, r2 = 1.f / s2, r3 = 1.f / s3;

    float4 acc[GPL];
#pragma unroll
    for (int g = 0; g < GPL; g++) acc[g] = make_float4(0.f, 0.f, 0.f, 0.f);
    int hsel[GPL];
#pragma unroll
    for (int g = 0; g < GPL; g++) hsel[g] = ((lane + 32 * g) * 4) / FOUT;

    for (int base = 0; base < deg; base += CAP) {
        int cnt = min(CAP, deg - base);
        for (int i = lane; i < cnt; i += 32) {
            int s = __ldg(&csrsrc[beg + base + i]);
            float4 a = __ldg((const float4*)&el[s * 4]);
            float4 ex;
            ex.x = __expf(lrelu(a.x + erv.x) - m0) * r0;
            ex.y = __expf(lrelu(a.y + erv.y) - m1) * r1;
            ex.z = __expf(lrelu(a.z + erv.z) - m2) * r2;
            ex.w = __expf(lrelu(a.w + erv.w) - m3) * r3;
            s_ex[wid][i] = ex;
        }
        __syncwarp();
#pragma unroll 2
        for (int i = 0; i < cnt; i++) {
            int s = __ldg(&csrsrc[beg + base + i]);
            float4 ex4 = s_ex[wid][i];
#pragma unroll
            for (int g = 0; g < GPL; g++) {
                int j4 = lane + 32 * g;
                if (G <= 32 || j4 < G) {
                    int h = hsel[g];
                    float a = (h == 0) ? ex4.x : (h == 1) ? ex4.y : (h == 2) ? ex4.z : ex4.w;
                    float4 zv = __ldg((const float4*)&z[s * KOUT + j4 * 4]);
                    acc[g].x += a * zv.x;
                    acc[g].y += a * zv.y;
                    acc[g].z += a * zv.z;
                    acc[g].w += a * zv.w;
                }
            }
        }
        __syncwarp();
    }

#pragma unroll
    for (int g = 0; g < GPL; g++) {
        int j4 = lane + 32 * g;
        if (G <= 32 || j4 < G) {
            float4 o = *(float4*)&out[node * KOUT + j4 * 4];
            o.x += acc[g].x;
            o.y += acc[g].y;
            o.z += acc[g].z;
            o.w += acc[g].w;
            *(float4*)&out[node * KOUT + j4 * 4] = o;
        }
    }
}

// ================= BatchNorm stats =================
__global__ void bn_init_kernel(float* __restrict__ sums) { sums[threadIdx.x] = 0.f; }

__global__ void bn_reduce_kernel(const float* __restrict__ x, float* __restrict__ sums,
                                 int n) {
    int c = threadIdx.x;
    int r0 = blockIdx.x * 256;
    int r1 = min(r0 + 256, n);
    float s = 0.f, s2 = 0.f;
    for (int r = r0; r < r1; r++) {
        float v = x[r * 128 + c];
        s += v;
        s2 += v * v;
    }
    atomicAdd(&sums[c], s);
    atomicAdd(&sums[128 + c], s2);
}

__global__ void bn_finalize_kernel(const float* __restrict__ sums, const float* __restrict__ g,
                                   const float* __restrict__ b, float* __restrict__ scale,
                                   float* __restrict__ shift, int n) {
    int c = threadIdx.x;   // 128
    float inv_n = 1.f / (float)n;
    float mean = sums[c] * inv_n;
    float var = sums[128 + c] * inv_n - mean * mean;
    float s = g[c] * rsqrtf(var + BN_EPS);
    scale[c] = s;
    shift[c] = b[c] - mean * s;
}

// ================= final: mean over heads + bias =================
__global__ void final_kernel(const float* __restrict__ buf, const float* __restrict__ bias,
                             float* __restrict__ out, int n) {
    int idx = blockIdx.x * blockDim.x + threadIdx.x;
    if (idx >= n * 40) return;
    int node = idx / 40;
    int c = idx - node * 40;
    const float* p = buf + node * 160;
    out[idx] = 0.25f * (p[c] + p[40 + c] + p[80 + c] + p[120 + c]) + bias[c];
}

// ---------------------------------------------------------------------------
extern "C" void kernel_launch(void* const* d_in, const int* in_sizes, int n_in,
                              void* d_out, int out_size) {
    const float* feat = (const float*)d_in[0];
    const int* src = (const int*)d_in[1];
    const int* dst = (const int*)d_in[2];
    const float* Wc[3] = {(const float*)d_in[3], (const float*)d_in[8], (const float*)d_in[13]};
    const float* al[3] = {(const float*)d_in[4], (const float*)d_in[9], (const float*)d_in[14]};
    const float* ar[3] = {(const float*)d_in[5], (const float*)d_in[10], (const float*)d_in[15]};
    const float* bc[3] = {(const float*)d_in[6], (const float*)d_in[11], (const float*)d_in[16]};
    const float* Wl[3] = {(const float*)d_in[7], (const float*)d_in[12], (const float*)d_in[17]};
    const float* g0 = (const float*)d_in[18];
    const float* b0 = (const float*)d_in[19];
    const float* g1 = (const float*)d_in[20];
    const float* b1 = (const float*)d_in[21];
    const float* bias_last = (const float*)d_in[22];

    const int n = in_sizes[0] / 128;  // 50000
    const int E = in_sizes[1];        // 800000

    float *z, *bufA, *bufB, *el, *er, *bnsum, *bnscale, *bnshift;
    int *deg, *rowptr, *wcur, *csrsrc, *bsum;
    __nv_bfloat16 *wthi, *wtlo;
    cudaGetSymbolAddress((void**)&z, g_z);
    cudaGetSymbolAddress((void**)&bufA, g_bufA);
    cudaGetSymbolAddress((void**)&bufB, g_bufB);
    cudaGetSymbolAddress((void**)&el, g_el);
    cudaGetSymbolAddress((void**)&er, g_er);
    cudaGetSymbolAddress((void**)&bnsum, g_bnsum);
    cudaGetSymbolAddress((void**)&bnscale, g_bnscale);
    cudaGetSymbolAddress((void**)&bnshift, g_bnshift);
    cudaGetSymbolAddress((void**)&deg, g_deg);
    cudaGetSymbolAddress((void**)&rowptr, g_rowptr);
    cudaGetSymbolAddress((void**)&wcur, g_wcur);
    cudaGetSymbolAddress((void**)&csrsrc, g_csrsrc);
    cudaGetSymbolAddress((void**)&bsum, g_bsum);
    cudaGetSymbolAddress((void**)&wthi, g_wthi);
    cudaGetSymbolAddress((void**)&wtlo, g_wtlo);
    const int WS = 160 * 128;

    const int edge_blocks = (E + 255) / 256;
    const int agg_blocks = (n + 7) / 8;
    const int gemm_grid = (n + 127) / 128;
    const int nb = (n + 1023) / 1024;   // 49

    const int smem128 = (256 + 256) * 136 * 2;  // 139264
    const int smem160 = (256 + 320) * 136 * 2;  // 156672
    cudaFuncSetAttribute(gemm_dual<128, 32, false>, cudaFuncAttributeMaxDynamicSharedMemorySize, smem128);
    cudaFuncSetAttribute(gemm_dual<128, 32, true>, cudaFuncAttributeMaxDynamicSharedMemorySize, smem128);
    cudaFuncSetAttribute(gemm_dual<160, 40, true>, cudaFuncAttributeMaxDynamicSharedMemorySize, smem160);

    // ---- CSR build (parallel scan) ----
    zero_deg_kernel<<<(n + 255) / 256, 256>>>(deg, n);
    count_kernel<<<edge_blocks, 256>>>(dst, deg, E);
    scan_partial<<<nb, 1024>>>(deg, rowptr, bsum, n);
    scan_tops<<<1, 32>>>(bsum, nb);
    scan_add<<<nb, 1024>>>(rowptr, bsum, wcur, n, nb);
    scatter_kernel<<<edge_blocks, 256>>>(src, dst, wcur, csrsrc, E);

    // ---- weight transpose + split ----
    const int Nk[3] = {128, 128, 160};
    for (int L = 0; L < 3; L++) {
        int NN = Nk[L], cnt = NN * 128;
        wsplit_kernel<<<(cnt + 255) / 256, 256>>>(Wc[L], wthi + (L * 2 + 0) * WS,
                                                  wtlo + (L * 2 + 0) * WS, NN, 128);
        wsplit_kernel<<<(cnt + 255) / 256, 256>>>(Wl[L], wthi + (L * 2 + 1) * WS,
                                                  wtlo + (L * 2 + 1) * WS, NN, 128);
    }

    // ---- layer 0: feat -> bufA ----
    gemm_dual<128, 32, false><<<gemm_grid, 256, smem128>>>(
        feat, wthi + 0 * WS, wtlo + 0 * WS, wthi + 1 * WS, wtlo + 1 * WS, bc[0],
        nullptr, nullptr, z, bufA, al[0], ar[0], el, er, n);
    node_agg_kernel<128, 32><<<agg_blocks, 256>>>(rowptr, csrsrc, el, er, z, bufA, n);
    bn_init_kernel<<<1, 256>>>(bnsum);
    bn_reduce_kernel<<<(n + 255) / 256, 128>>>(bufA, bnsum, n);
    bn_finalize_kernel<<<1, 128>>>(bnsum, g0, b0, bnscale, bnshift, n);

    // ---- layer 1: bufA (BN applied in A-fill) -> bufB ----
    gemm_dual<128, 32, true><<<gemm_grid, 256, smem128>>>(
        bufA, wthi + 2 * WS, wtlo + 2 * WS, wthi + 3 * WS, wtlo + 3 * WS, bc[1],
        bnscale, bnshift, z, bufB, al[1], ar[1], el, er, n);
    node_agg_kernel<128, 32><<<agg_blocks, 256>>>(rowptr, csrsrc, el, er, z, bufB, n);
    bn_init_kernel<<<1, 256>>>(bnsum);
    bn_reduce_kernel<<<(n + 255) / 256, 128>>>(bufB, bnsum, n);
    bn_finalize_kernel<<<1, 128>>>(bnsum, g1, b1, bnscale, bnshift, n);

    // ---- layer 2: bufB (BN in A-fill) -> bufA (160 cols) ----
    gemm_dual<160, 40, true><<<gemm_grid, 256, smem160>>>(
        bufB, wthi + 4 * WS, wtlo + 4 * WS, wthi + 5 * WS, wtlo + 5 * WS, bc[2],
        bnscale, bnshift, z, bufA, al[2], ar[2], el, er, n);
    node_agg_kernel<160, 40><<<agg_blocks, 256>>>(rowptr, csrsrc, el, er, z, bufA, n);

    // ---- epilogue ----
    final_kernel<<<(n * 40 + 255) / 256, 256>>>(bufA, bias_last, (float*)d_out, n);
}